// round 13
// baseline (speedup 1.0000x reference)
#include <cuda_runtime.h>

// Problem constants
#define H_   128
#define W_   128
#define C_   32
#define B_   4
#define OH_  120
#define OW_  120
#define OCH_ 100
#define F_   64

__device__ float g_offbuf[(size_t)B_ * OH_ * OW_ * OCH_];
// tf32 fragment-ordered offset-conv weights: [k][s][t13][lane][r]
__device__ unsigned g_bpack[25 * 4 * 13 * 32 * 2];      // 83200
// tf32 fragment-ordered dcn weights: [k][g][s][t4][lane][r]
__device__ unsigned g_wdpack[25 * 2 * 4 * 4 * 32 * 2];  // 51200

// ---- packed f32x2 helpers --------------------------------------------------
typedef unsigned long long u64t;

__device__ __forceinline__ u64t ffma2(u64t a, u64t b, u64t c) {
    u64t d;
    asm("fma.rn.f32x2 %0, %1, %2, %3;" : "=l"(d) : "l"(a), "l"(b), "l"(c));
    return d;
}
__device__ __forceinline__ u64t fmul2(u64t a, u64t b) {
    u64t d;
    asm("mul.rn.f32x2 %0, %1, %2;" : "=l"(d) : "l"(a), "l"(b));
    return d;
}
__device__ __forceinline__ u64t dup2(float x) {
    u64t d; unsigned xi = __float_as_uint(x);
    asm("mov.b64 %0, {%1, %1};" : "=l"(d) : "r"(xi));
    return d;
}
__device__ __forceinline__ float2 up2(u64t v) {
    float2 f;
    asm("mov.b64 {%0, %1}, %2;" : "=f"(f.x), "=f"(f.y) : "l"(v));
    return f;
}
union f4u { float4 f; ulonglong2 u; };

__device__ __forceinline__ unsigned f2tf32(float x) {
    unsigned r;
    asm("cvt.rna.tf32.f32 %0, %1;" : "=r"(r) : "f"(x));
    return r;
}

// ---------------------------------------------------------------------------
// Prepass: pack BOTH weight tensors into tf32 mma B-fragment order.
// ---------------------------------------------------------------------------
#define NPACK_OFF (25 * 4 * 13 * 32 * 2)
#define NPACK_DCN (25 * 2 * 4 * 4 * 32 * 2)

__global__ void pack_weights_kernel(const float* __restrict__ w_off,
                                    const float* __restrict__ w_dcn)
{
    int idx = blockIdx.x * 256 + threadIdx.x;
    if (idx < NPACK_OFF) {
        int r    = idx & 1;
        int lane = (idx >> 1) & 31;
        int rem  = idx >> 6;
        int t    = rem % 13;
        int s    = (rem / 13) % 4;
        int k    = rem / (13 * 4);
        int tig  = lane & 3;
        int g8   = lane >> 2;
        int c    = 8 * s + tig + 4 * r;
        int ch   = 8 * t + g8;
        float v  = (ch < 100) ? w_off[k * 3200 + c * 100 + ch] : 0.0f;
        g_bpack[idx] = f2tf32(v);
    } else if (idx < NPACK_OFF + NPACK_DCN) {
        int j    = idx - NPACK_OFF;
        int r    = j & 1;
        int lane = (j >> 1) & 31;
        int rem  = j >> 6;
        int t    = rem % 4;
        int s    = (rem / 4) % 4;
        int g    = (rem / 16) % 2;
        int k    = rem / 32;
        int tig  = lane & 3;
        int g8   = lane >> 2;
        int c    = 8 * s + tig + 4 * r;
        int o    = 32 * g + 8 * t + g8;
        g_wdpack[j] = f2tf32(w_dcn[k * 2048 + c * 64 + o]);
    }
}

// ---------------------------------------------------------------------------
// Kernel A v8 (unchanged, ~60us): offset conv via tf32 mma.sync.m16n8k8.
// ---------------------------------------------------------------------------
#define PXS 36   // pixel stride in patch (floats)

__global__ __launch_bounds__(128, 5)
void offset_conv_kernel(const float* __restrict__ vol,
                        const float* __restrict__ b_off)
{
    __shared__ float patch[16 * 16 * PXS];   // 36.9 KB

    const int tid  = threadIdx.x;
    const int lane = tid & 31;
    const int warp = tid >> 5;
    const int ox0 = blockIdx.x * 8;
    const int oy0 = blockIdx.y * 8;
    const int b   = blockIdx.z;

    for (int idx = tid; idx < 2048; idx += 128) {
        int row = idx >> 7;
        int rem = idx & 127;
        int col = rem >> 3;
        int c4  = rem & 7;
        const float4 v = *reinterpret_cast<const float4*>(
            vol + ((size_t)((b * H_ + oy0 + row) * W_ + ox0 + col)) * C_ + 4 * c4);
        *reinterpret_cast<float4*>(&patch[(row * 16 + col) * PXS + 4 * c4]) = v;
    }
    __syncthreads();

    const int g   = lane >> 2;
    const int tig = lane & 3;

    float cacc[13][4];
#pragma unroll
    for (int t = 0; t < 13; ++t)
#pragma unroll
        for (int i = 0; i < 4; ++i) cacc[t][i] = 0.0f;

    const unsigned* bp = g_bpack + 2 * lane;

#pragma unroll 1
    for (int k = 0; k < 25; ++k) {
        const int fy2 = (k / 5) * 2, fx2 = (k % 5) * 2;
        const float* pa0 = &patch[((2 * warp + fy2) * 16 + fx2 + g) * PXS];
        const float* pa1 = pa0 + 16 * PXS;

#pragma unroll
        for (int s = 0; s < 4; ++s) {
            unsigned a0 = f2tf32(pa0[8 * s + tig]);
            unsigned a1 = f2tf32(pa1[8 * s + tig]);
            unsigned a2 = f2tf32(pa0[8 * s + tig + 4]);
            unsigned a3 = f2tf32(pa1[8 * s + tig + 4]);
            const uint2* bks = reinterpret_cast<const uint2*>(
                bp + ((k * 4 + s) * 13) * 64);
#pragma unroll
            for (int t = 0; t < 13; ++t) {
                uint2 bb = __ldg(bks + t * 32);
                asm volatile(
                    "mma.sync.aligned.m16n8k8.row.col.f32.tf32.tf32.f32 "
                    "{%0,%1,%2,%3}, {%4,%5,%6,%7}, {%8,%9}, {%0,%1,%2,%3};"
                    : "+f"(cacc[t][0]), "+f"(cacc[t][1]),
                      "+f"(cacc[t][2]), "+f"(cacc[t][3])
                    : "r"(a0), "r"(a1), "r"(a2), "r"(a3),
                      "r"(bb.x), "r"(bb.y));
            }
        }
    }

    const int oyA = oy0 + 2 * warp;
    const int oxA = ox0 + g;
    float* outA = &g_offbuf[((size_t)((b * OH_ + oyA) * OW_ + oxA)) * OCH_];
    float* outB = outA + (size_t)OW_ * OCH_;
#pragma unroll
    for (int t = 0; t < 13; ++t) {
        int ch0 = 8 * t + 2 * tig;
        if (ch0 < 100) {
            float2 bo = *reinterpret_cast<const float2*>(b_off + ch0);
            *reinterpret_cast<float2*>(outA + ch0) =
                make_float2(cacc[t][0] + bo.x, cacc[t][1] + bo.y);
            *reinterpret_cast<float2*>(outB + ch0) =
                make_float2(cacc[t][2] + bo.x, cacc[t][3] + bo.y);
        }
    }
}

// ---------------------------------------------------------------------------
// Kernel B v9: software-pipelined gather + tf32 MMA GEMM.
// Per sync interval: issue tap k+1's 16 LDG.128 (in-flight regs), run tap k's
// GEMM (hides the LDG latency), then blend+STS tap k+1, one sync.
// Tile 4y x 8x = 32 px, 128 threads, grid 1800. Double-buffered Ss (tf32
// bits, [g][px][c] stride 36); offsets staged in smem once.
// ---------------------------------------------------------------------------
#define GST (32 * PXS + 8)    // 1160: group stride in Ss
#define OFS 104               // offset row stride (floats)

__global__ __launch_bounds__(128, 5)
void dcn_kernel(const float* __restrict__ vol,
                const float* __restrict__ b_dcn,
                float* __restrict__ out)
{
    __shared__ __align__(16) float Ss[2][2 * GST];   // 18.6 KB (tf32 bits)
    __shared__ __align__(16) float offS[32 * OFS];   // 13.3 KB

    const int tid  = threadIdx.x;
    const int lane = tid & 31;
    const int warp = tid >> 5;
    const int ox0 = blockIdx.x * 8;
    const int oy0 = blockIdx.y * 4;
    const int b   = blockIdx.z;

    // GEMM roles
    const int gw  = warp >> 1;
    const int mh  = warp & 1;
    const int g8  = lane >> 2;
    const int tig = lane & 3;

    // Gather roles (4 passes x 4 samples x 8 lanes)
    const int q = lane >> 3;
    const int j = lane & 7;
    const int sBase = warp * 16;

    const float* volb = vol + (size_t)b * (H_ * W_ * C_);
    const float* offb = g_offbuf + ((size_t)(b * OH_ + oy0) * OW_ + ox0) * OCH_;

    // Stage the tile's 32x100 offsets once
    for (int idx = tid; idx < 3200; idx += 128) {
        int p  = idx / 100;
        int ch = idx - p * 100;
        int pyi = p >> 3, pxi = p & 7;
        offS[p * OFS + ch] = __ldg(offb + (pyi * OW_ + pxi) * OCH_ + ch);
    }
    __syncthreads();

    float cacc[4][4];
#pragma unroll
    for (int t = 0; t < 4; ++t)
#pragma unroll
        for (int i = 0; i < 4; ++i) cacc[t][i] = 0.0f;

    const unsigned* wdp = g_wdpack + 2 * lane;

    // In-flight gather state (16 float4 + 8 floats)
    f4u L[4][4];
    float wyA[4], wxA[4];

    // ---- loads(kk): issue offset LDS + 16 volume LDG.128 for tap kk -------
    auto loads = [&](int kk) {
        const int fy = kk / 5, fx = kk - fy * 5;
        const float dky = (float)((fy - 2) * 2);
        const float dkx = (float)((fx - 2) * 2);
#pragma unroll
        for (int pass = 0; pass < 4; ++pass) {
            int s = sBase + pass * 4 + q;
            int p = s & 31, g2 = s >> 5;
            int pyi = p >> 3, pxi = p & 7;

            float4 ov = *reinterpret_cast<const float4*>(&offS[p * OFS + 4 * kk]);
            float offy = g2 ? ov.y : ov.x;
            float offx = g2 ? ov.w : ov.z;

            float py = (float)(oy0 + pyi + 4) + dky + offy;
            float px = (float)(ox0 + pxi + 4) + dkx + offx;
            py = fminf(fmaxf(py, 0.0f), 127.0f);
            px = fminf(fmaxf(px, 0.0f), 127.0f);
            float y0f = fminf(floorf(py), 126.0f);
            float x0f = fminf(floorf(px), 126.0f);
            wyA[pass] = py - y0f;
            wxA[pass] = px - x0f;
            int y0 = (int)y0f, x0 = (int)x0f;

            const float4* r0 = reinterpret_cast<const float4*>(
                volb + ((size_t)(y0 * W_ + x0)) * C_);
            L[pass][0].f = r0[j];
            L[pass][1].f = r0[j + 8];
            L[pass][2].f = r0[j + 1024];
            L[pass][3].f = r0[j + 1032];
        }
    };

    // ---- blend_sts(kk): blend the in-flight loads, convert tf32, STS ------
    auto blend_sts = [&](int kk) {
        float* Sb = Ss[kk & 1];
#pragma unroll
        for (int pass = 0; pass < 4; ++pass) {
            int s = sBase + pass * 4 + q;
            int p = s & 31, g2 = s >> 5;
            float wy = wyA[pass], wx = wxA[pass];
            u64t c00p = dup2((1.0f - wy) * (1.0f - wx));
            u64t c01p = dup2((1.0f - wy) * wx);
            u64t c10p = dup2(wy * (1.0f - wx));
            u64t c11p = dup2(wy * wx);

            ulonglong2 svu;
            svu.x = ffma2(L[pass][0].u.x, c00p, ffma2(L[pass][1].u.x, c01p,
                        ffma2(L[pass][2].u.x, c10p, fmul2(L[pass][3].u.x, c11p))));
            svu.y = ffma2(L[pass][0].u.y, c00p, ffma2(L[pass][1].u.y, c01p,
                        ffma2(L[pass][2].u.y, c10p, fmul2(L[pass][3].u.y, c11p))));
            float2 s01 = up2(svu.x);
            float2 s23 = up2(svu.y);

            uint4 sv;
            sv.x = f2tf32(s01.x);
            sv.y = f2tf32(s01.y);
            sv.z = f2tf32(s23.x);
            sv.w = f2tf32(s23.y);
            *reinterpret_cast<uint4*>(&Sb[g2 * GST + p * PXS + 4 * j]) = sv;
        }
    };

    // ---- gemm(kk): 16 MMAs from Ss[kk&1] -----------------------------------
    auto gemm = [&](int kk) {
        const unsigned* Sg  = reinterpret_cast<const unsigned*>(
            Ss[kk & 1] + gw * GST + (16 * mh + g8) * PXS);
        const unsigned* Sg8 = Sg + 8 * PXS;
        const unsigned* wk = wdp + ((kk * 2 + gw) * 16) * 64;
#pragma unroll
        for (int s = 0; s < 4; ++s) {
            unsigned a0 = Sg [8 * s + tig];
            unsigned a1 = Sg8[8 * s + tig];
            unsigned a2 = Sg [8 * s + tig + 4];
            unsigned a3 = Sg8[8 * s + tig + 4];
            const uint2* bks = reinterpret_cast<const uint2*>(wk + (s * 4) * 64);
#pragma unroll
            for (int t = 0; t < 4; ++t) {
                uint2 bb = __ldg(bks + t * 32);
                asm volatile(
                    "mma.sync.aligned.m16n8k8.row.col.f32.tf32.tf32.f32 "
                    "{%0,%1,%2,%3}, {%4,%5,%6,%7}, {%8,%9}, {%0,%1,%2,%3};"
                    : "+f"(cacc[t][0]), "+f"(cacc[t][1]),
                      "+f"(cacc[t][2]), "+f"(cacc[t][3])
                    : "r"(a0), "r"(a1), "r"(a2), "r"(a3),
                      "r"(bb.x), "r"(bb.y));
            }
        }
    };

    // Prologue: fill buffer 0
    loads(0);
    blend_sts(0);
    __syncthreads();

#pragma unroll 1
    for (int k = 0; k < 25; ++k) {
        if (k < 24) loads(k + 1);     // long-latency LDGs in flight
        gemm(k);                      // independent work hides them
        if (k < 24) blend_sts(k + 1);
        __syncthreads();
    }

    // Epilogue: C rows = px 16mh+g8 (+8), cols = out 32gw+8t+2tig (+1)
    const int pA = 16 * mh + g8;
    const int pB = pA + 8;
    const int oyA = oy0 + (pA >> 3), oxA = ox0 + (pA & 7);
    const int oyB = oy0 + (pB >> 3), oxB = ox0 + (pB & 7);
    float* outA = out + ((size_t)((b * OH_ + oyA) * OW_ + oxA)) * F_;
    float* outB = out + ((size_t)((b * OH_ + oyB) * OW_ + oxB)) * F_;
#pragma unroll
    for (int t = 0; t < 4; ++t) {
        int o0 = 32 * gw + 8 * t + 2 * tig;
        float2 bo = __ldg(reinterpret_cast<const float2*>(b_dcn + o0));
        *reinterpret_cast<float2*>(outA + o0) =
            make_float2(cacc[t][0] + bo.x, cacc[t][1] + bo.y);
        *reinterpret_cast<float2*>(outB + o0) =
            make_float2(cacc[t][2] + bo.x, cacc[t][3] + bo.y);
    }
}

// ---------------------------------------------------------------------------
extern "C" void kernel_launch(void* const* d_in, const int* in_sizes, int n_in,
                              void* d_out, int out_size)
{
    const float* vol   = (const float*)d_in[0];
    const float* w_off = (const float*)d_in[1];
    const float* b_off = (const float*)d_in[2];
    const float* w_dcn = (const float*)d_in[3];
    const float* b_dcn = (const float*)d_in[4];
    float* out = (float*)d_out;

    pack_weights_kernel<<<(NPACK_OFF + NPACK_DCN + 255) / 256, 256>>>(w_off, w_dcn);

    dim3 gA(OW_ / 8, OH_ / 8, B_);   // (15, 15, 4)
    offset_conv_kernel<<<gA, 128>>>(vol, b_off);

    dim3 gB(OW_ / 8, OH_ / 4, B_);   // (15, 30, 4) = 1800 blocks
    dcn_kernel<<<gB, 128>>>(vol, b_dcn, out);
}

// round 14
// speedup vs baseline: 1.2445x; 1.2445x over previous
#include <cuda_runtime.h>

// Problem constants
#define H_   128
#define W_   128
#define C_   32
#define B_   4
#define OH_  120
#define OW_  120
#define OCH_ 100
#define F_   64

__device__ float g_offbuf[(size_t)B_ * OH_ * OW_ * OCH_];
// tf32 fragment-ordered offset-conv weights: [k][s][t13][lane][r]
__device__ unsigned g_bpack[25 * 4 * 13 * 32 * 2];      // 83200
// tf32 fragment-ordered dcn weights: [k][g][s][t4][lane][r]
__device__ unsigned g_wdpack[25 * 2 * 4 * 4 * 32 * 2];  // 51200

// ---- packed f32x2 helpers --------------------------------------------------
typedef unsigned long long u64t;

__device__ __forceinline__ u64t ffma2(u64t a, u64t b, u64t c) {
    u64t d;
    asm("fma.rn.f32x2 %0, %1, %2, %3;" : "=l"(d) : "l"(a), "l"(b), "l"(c));
    return d;
}
__device__ __forceinline__ u64t fmul2(u64t a, u64t b) {
    u64t d;
    asm("mul.rn.f32x2 %0, %1, %2;" : "=l"(d) : "l"(a), "l"(b));
    return d;
}
__device__ __forceinline__ u64t dup2(float x) {
    u64t d; unsigned xi = __float_as_uint(x);
    asm("mov.b64 %0, {%1, %1};" : "=l"(d) : "r"(xi));
    return d;
}
__device__ __forceinline__ float2 up2(u64t v) {
    float2 f;
    asm("mov.b64 {%0, %1}, %2;" : "=f"(f.x), "=f"(f.y) : "l"(v));
    return f;
}
union f4u { float4 f; ulonglong2 u; };

__device__ __forceinline__ unsigned f2tf32(float x) {
    unsigned r;
    asm("cvt.rna.tf32.f32 %0, %1;" : "=r"(r) : "f"(x));
    return r;
}

// ---------------------------------------------------------------------------
// Prepass: pack BOTH weight tensors into tf32 mma B-fragment order.
// ---------------------------------------------------------------------------
#define NPACK_OFF (25 * 4 * 13 * 32 * 2)
#define NPACK_DCN (25 * 2 * 4 * 4 * 32 * 2)

__global__ void pack_weights_kernel(const float* __restrict__ w_off,
                                    const float* __restrict__ w_dcn)
{
    int idx = blockIdx.x * 256 + threadIdx.x;
    if (idx < NPACK_OFF) {
        int r    = idx & 1;
        int lane = (idx >> 1) & 31;
        int rem  = idx >> 6;
        int t    = rem % 13;
        int s    = (rem / 13) % 4;
        int k    = rem / (13 * 4);
        int tig  = lane & 3;
        int g8   = lane >> 2;
        int c    = 8 * s + tig + 4 * r;
        int ch   = 8 * t + g8;
        float v  = (ch < 100) ? w_off[k * 3200 + c * 100 + ch] : 0.0f;
        g_bpack[idx] = f2tf32(v);
    } else if (idx < NPACK_OFF + NPACK_DCN) {
        int j    = idx - NPACK_OFF;
        int r    = j & 1;
        int lane = (j >> 1) & 31;
        int rem  = j >> 6;
        int t    = rem % 4;
        int s    = (rem / 4) % 4;
        int g    = (rem / 16) % 2;
        int k    = rem / 32;
        int tig  = lane & 3;
        int g8   = lane >> 2;
        int c    = 8 * s + tig + 4 * r;
        int o    = 32 * g + 8 * t + g8;
        g_wdpack[j] = f2tf32(w_dcn[k * 2048 + c * 64 + o]);
    }
}

// ---------------------------------------------------------------------------
// Kernel A v8 (unchanged, ~60us): offset conv via tf32 mma.sync.m16n8k8.
// ---------------------------------------------------------------------------
#define PXS 36   // pixel stride in patch (floats)

__global__ __launch_bounds__(128, 5)
void offset_conv_kernel(const float* __restrict__ vol,
                        const float* __restrict__ b_off)
{
    __shared__ float patch[16 * 16 * PXS];   // 36.9 KB

    const int tid  = threadIdx.x;
    const int lane = tid & 31;
    const int warp = tid >> 5;
    const int ox0 = blockIdx.x * 8;
    const int oy0 = blockIdx.y * 8;
    const int b   = blockIdx.z;

    for (int idx = tid; idx < 2048; idx += 128) {
        int row = idx >> 7;
        int rem = idx & 127;
        int col = rem >> 3;
        int c4  = rem & 7;
        const float4 v = *reinterpret_cast<const float4*>(
            vol + ((size_t)((b * H_ + oy0 + row) * W_ + ox0 + col)) * C_ + 4 * c4);
        *reinterpret_cast<float4*>(&patch[(row * 16 + col) * PXS + 4 * c4]) = v;
    }
    __syncthreads();

    const int g   = lane >> 2;
    const int tig = lane & 3;

    float cacc[13][4];
#pragma unroll
    for (int t = 0; t < 13; ++t)
#pragma unroll
        for (int i = 0; i < 4; ++i) cacc[t][i] = 0.0f;

    const unsigned* bp = g_bpack + 2 * lane;

#pragma unroll 1
    for (int k = 0; k < 25; ++k) {
        const int fy2 = (k / 5) * 2, fx2 = (k % 5) * 2;
        const float* pa0 = &patch[((2 * warp + fy2) * 16 + fx2 + g) * PXS];
        const float* pa1 = pa0 + 16 * PXS;

#pragma unroll
        for (int s = 0; s < 4; ++s) {
            unsigned a0 = f2tf32(pa0[8 * s + tig]);
            unsigned a1 = f2tf32(pa1[8 * s + tig]);
            unsigned a2 = f2tf32(pa0[8 * s + tig + 4]);
            unsigned a3 = f2tf32(pa1[8 * s + tig + 4]);
            const uint2* bks = reinterpret_cast<const uint2*>(
                bp + ((k * 4 + s) * 13) * 64);
#pragma unroll
            for (int t = 0; t < 13; ++t) {
                uint2 bb = __ldg(bks + t * 32);
                asm volatile(
                    "mma.sync.aligned.m16n8k8.row.col.f32.tf32.tf32.f32 "
                    "{%0,%1,%2,%3}, {%4,%5,%6,%7}, {%8,%9}, {%0,%1,%2,%3};"
                    : "+f"(cacc[t][0]), "+f"(cacc[t][1]),
                      "+f"(cacc[t][2]), "+f"(cacc[t][3])
                    : "r"(a0), "r"(a1), "r"(a2), "r"(a3),
                      "r"(bb.x), "r"(bb.y));
            }
        }
    }

    const int oyA = oy0 + 2 * warp;
    const int oxA = ox0 + g;
    float* outA = &g_offbuf[((size_t)((b * OH_ + oyA) * OW_ + oxA)) * OCH_];
    float* outB = outA + (size_t)OW_ * OCH_;
#pragma unroll
    for (int t = 0; t < 13; ++t) {
        int ch0 = 8 * t + 2 * tig;
        if (ch0 < 100) {
            float2 bo = *reinterpret_cast<const float2*>(b_off + ch0);
            *reinterpret_cast<float2*>(outA + ch0) =
                make_float2(cacc[t][0] + bo.x, cacc[t][1] + bo.y);
            *reinterpret_cast<float2*>(outB + ch0) =
                make_float2(cacc[t][2] + bo.x, cacc[t][3] + bo.y);
        }
    }
}

// ---------------------------------------------------------------------------
// Kernel B v10: HALF-granularity software pipeline (spill-free).
// Per tap: loads-half(k+1) [8 LDG.128 in flight, 32 regs] -> gemm-half(k)
// [8 MMAs hide them] -> blend+STS-half(k+1), twice; one sync/tap.
// Tile 4y x 8x = 32 px, 128 threads, grid 1800. Double-buffered Ss (tf32
// bits, [g][px][c] stride 36); offsets staged in smem once.
// ---------------------------------------------------------------------------
#define GST (32 * PXS + 8)    // 1160: group stride in Ss
#define OFS 104               // offset row stride (floats)

__global__ __launch_bounds__(128, 5)
void dcn_kernel(const float* __restrict__ vol,
                const float* __restrict__ b_dcn,
                float* __restrict__ out)
{
    __shared__ __align__(16) float Ss[2][2 * GST];   // 18.6 KB (tf32 bits)
    __shared__ __align__(16) float offS[32 * OFS];   // 13.3 KB

    const int tid  = threadIdx.x;
    const int lane = tid & 31;
    const int warp = tid >> 5;
    const int ox0 = blockIdx.x * 8;
    const int oy0 = blockIdx.y * 4;
    const int b   = blockIdx.z;

    // GEMM roles
    const int gw  = warp >> 1;
    const int mh  = warp & 1;
    const int g8  = lane >> 2;
    const int tig = lane & 3;

    // Gather roles (4 passes x 4 samples x 8 lanes)
    const int q = lane >> 3;
    const int j = lane & 7;
    const int sBase = warp * 16;

    const float* volb = vol + (size_t)b * (H_ * W_ * C_);
    const float* offb = g_offbuf + ((size_t)(b * OH_ + oy0) * OW_ + ox0) * OCH_;

    // Stage the tile's 32x100 offsets once
    for (int idx = tid; idx < 3200; idx += 128) {
        int p  = idx / 100;
        int ch = idx - p * 100;
        int pyi = p >> 3, pxi = p & 7;
        offS[p * OFS + ch] = __ldg(offb + (pyi * OW_ + pxi) * OCH_ + ch);
    }
    __syncthreads();

    float cacc[4][4];
#pragma unroll
    for (int t = 0; t < 4; ++t)
#pragma unroll
        for (int i = 0; i < 4; ++i) cacc[t][i] = 0.0f;

    const unsigned* wdp = g_wdpack + 2 * lane;

    // In-flight gather state: 2 passes (8 float4 = 32 regs)
    f4u L[2][4];
    float wyA[2], wxA[2];

    // ---- loads_half(kk, h): issue 8 LDG.128 for passes {2h, 2h+1} ----------
    auto loads_half = [&](int kk, int h) {
        const int fy = kk / 5, fx = kk - fy * 5;
        const float dky = (float)((fy - 2) * 2);
        const float dkx = (float)((fx - 2) * 2);
#pragma unroll
        for (int u = 0; u < 2; ++u) {
            int pass = 2 * h + u;
            int s = sBase + pass * 4 + q;
            int p = s & 31, g2 = s >> 5;
            int pyi = p >> 3, pxi = p & 7;

            float4 ov = *reinterpret_cast<const float4*>(&offS[p * OFS + 4 * kk]);
            float offy = g2 ? ov.y : ov.x;
            float offx = g2 ? ov.w : ov.z;

            float py = (float)(oy0 + pyi + 4) + dky + offy;
            float px = (float)(ox0 + pxi + 4) + dkx + offx;
            py = fminf(fmaxf(py, 0.0f), 127.0f);
            px = fminf(fmaxf(px, 0.0f), 127.0f);
            float y0f = fminf(floorf(py), 126.0f);
            float x0f = fminf(floorf(px), 126.0f);
            wyA[u] = py - y0f;
            wxA[u] = px - x0f;
            int y0 = (int)y0f, x0 = (int)x0f;

            const float4* r0 = reinterpret_cast<const float4*>(
                volb + ((size_t)(y0 * W_ + x0)) * C_);
            L[u][0].f = r0[j];
            L[u][1].f = r0[j + 8];
            L[u][2].f = r0[j + 1024];
            L[u][3].f = r0[j + 1032];
        }
    };

    // ---- blend_half(kk, h): blend passes {2h, 2h+1}, convert tf32, STS ----
    auto blend_half = [&](int kk, int h) {
        float* Sb = Ss[kk & 1];
#pragma unroll
        for (int u = 0; u < 2; ++u) {
            int pass = 2 * h + u;
            int s = sBase + pass * 4 + q;
            int p = s & 31, g2 = s >> 5;
            float wy = wyA[u], wx = wxA[u];
            u64t c00p = dup2((1.0f - wy) * (1.0f - wx));
            u64t c01p = dup2((1.0f - wy) * wx);
            u64t c10p = dup2(wy * (1.0f - wx));
            u64t c11p = dup2(wy * wx);

            ulonglong2 svu;
            svu.x = ffma2(L[u][0].u.x, c00p, ffma2(L[u][1].u.x, c01p,
                        ffma2(L[u][2].u.x, c10p, fmul2(L[u][3].u.x, c11p))));
            svu.y = ffma2(L[u][0].u.y, c00p, ffma2(L[u][1].u.y, c01p,
                        ffma2(L[u][2].u.y, c10p, fmul2(L[u][3].u.y, c11p))));
            float2 s01 = up2(svu.x);
            float2 s23 = up2(svu.y);

            uint4 sv;
            sv.x = f2tf32(s01.x);
            sv.y = f2tf32(s01.y);
            sv.z = f2tf32(s23.x);
            sv.w = f2tf32(s23.y);
            *reinterpret_cast<uint4*>(&Sb[g2 * GST + p * PXS + 4 * j]) = sv;
        }
    };

    // ---- gemm_half(kk, h): 8 MMAs for k-steps {2h, 2h+1} ------------------
    auto gemm_half = [&](int kk, int h) {
        const unsigned* Sg  = reinterpret_cast<const unsigned*>(
            Ss[kk & 1] + gw * GST + (16 * mh + g8) * PXS);
        const unsigned* Sg8 = Sg + 8 * PXS;
        const unsigned* wk = wdp + ((kk * 2 + gw) * 16) * 64;
#pragma unroll
        for (int u = 0; u < 2; ++u) {
            int s = 2 * h + u;
            unsigned a0 = Sg [8 * s + tig];
            unsigned a1 = Sg8[8 * s + tig];
            unsigned a2 = Sg [8 * s + tig + 4];
            unsigned a3 = Sg8[8 * s + tig + 4];
            const uint2* bks = reinterpret_cast<const uint2*>(wk + (s * 4) * 64);
#pragma unroll
            for (int t = 0; t < 4; ++t) {
                uint2 bb = __ldg(bks + t * 32);
                asm volatile(
                    "mma.sync.aligned.m16n8k8.row.col.f32.tf32.tf32.f32 "
                    "{%0,%1,%2,%3}, {%4,%5,%6,%7}, {%8,%9}, {%0,%1,%2,%3};"
                    : "+f"(cacc[t][0]), "+f"(cacc[t][1]),
                      "+f"(cacc[t][2]), "+f"(cacc[t][3])
                    : "r"(a0), "r"(a1), "r"(a2), "r"(a3),
                      "r"(bb.x), "r"(bb.y));
            }
        }
    };

    // Prologue: fill buffer 0
    loads_half(0, 0); blend_half(0, 0);
    loads_half(0, 1); blend_half(0, 1);
    __syncthreads();

#pragma unroll 1
    for (int k = 0; k < 25; ++k) {
        if (k < 24) loads_half(k + 1, 0);
        gemm_half(k, 0);
        if (k < 24) blend_half(k + 1, 0);
        if (k < 24) loads_half(k + 1, 1);
        gemm_half(k, 1);
        if (k < 24) blend_half(k + 1, 1);
        __syncthreads();
    }

    // Epilogue: C rows = px 16mh+g8 (+8), cols = out 32gw+8t+2tig (+1)
    const int pA = 16 * mh + g8;
    const int pB = pA + 8;
    const int oyA = oy0 + (pA >> 3), oxA = ox0 + (pA & 7);
    const int oyB = oy0 + (pB >> 3), oxB = ox0 + (pB & 7);
    float* outA = out + ((size_t)((b * OH_ + oyA) * OW_ + oxA)) * F_;
    float* outB = out + ((size_t)((b * OH_ + oyB) * OW_ + oxB)) * F_;
#pragma unroll
    for (int t = 0; t < 4; ++t) {
        int o0 = 32 * gw + 8 * t + 2 * tig;
        float2 bo = __ldg(reinterpret_cast<const float2*>(b_dcn + o0));
        *reinterpret_cast<float2*>(outA + o0) =
            make_float2(cacc[t][0] + bo.x, cacc[t][1] + bo.y);
        *reinterpret_cast<float2*>(outB + o0) =
            make_float2(cacc[t][2] + bo.x, cacc[t][3] + bo.y);
    }
}

// ---------------------------------------------------------------------------
extern "C" void kernel_launch(void* const* d_in, const int* in_sizes, int n_in,
                              void* d_out, int out_size)
{
    const float* vol   = (const float*)d_in[0];
    const float* w_off = (const float*)d_in[1];
    const float* b_off = (const float*)d_in[2];
    const float* w_dcn = (const float*)d_in[3];
    const float* b_dcn = (const float*)d_in[4];
    float* out = (float*)d_out;

    pack_weights_kernel<<<(NPACK_OFF + NPACK_DCN + 255) / 256, 256>>>(w_off, w_dcn);

    dim3 gA(OW_ / 8, OH_ / 8, B_);   // (15, 15, 4)
    offset_conv_kernel<<<gA, 128>>>(vol, b_off);

    dim3 gB(OW_ / 8, OH_ / 4, B_);   // (15, 30, 4) = 1800 blocks
    dcn_kernel<<<gB, 128>>>(vol, b_dcn, out);
}

// round 15
// speedup vs baseline: 1.4256x; 1.1455x over previous
#include <cuda_runtime.h>

// Problem constants
#define H_   128
#define W_   128
#define C_   32
#define B_   4
#define OH_  120
#define OW_  120
#define OCH_ 100
#define F_   64

__device__ float g_offbuf[(size_t)B_ * OH_ * OW_ * OCH_];
// tf32 fragment-ordered offset-conv weights: [k][s][t13][lane][r]
__device__ unsigned g_bpack[25 * 4 * 13 * 32 * 2];      // 83200
// tf32 fragment-ordered dcn weights: [k][g][s][t4][lane][r]
__device__ unsigned g_wdpack[25 * 2 * 4 * 4 * 32 * 2];  // 51200

// ---- packed f32x2 helpers --------------------------------------------------
typedef unsigned long long u64t;

__device__ __forceinline__ u64t ffma2(u64t a, u64t b, u64t c) {
    u64t d;
    asm("fma.rn.f32x2 %0, %1, %2, %3;" : "=l"(d) : "l"(a), "l"(b), "l"(c));
    return d;
}
__device__ __forceinline__ u64t fmul2(u64t a, u64t b) {
    u64t d;
    asm("mul.rn.f32x2 %0, %1, %2;" : "=l"(d) : "l"(a), "l"(b));
    return d;
}
__device__ __forceinline__ u64t dup2(float x) {
    u64t d; unsigned xi = __float_as_uint(x);
    asm("mov.b64 %0, {%1, %1};" : "=l"(d) : "r"(xi));
    return d;
}
__device__ __forceinline__ float2 up2(u64t v) {
    float2 f;
    asm("mov.b64 {%0, %1}, %2;" : "=f"(f.x), "=f"(f.y) : "l"(v));
    return f;
}
union f4u { float4 f; ulonglong2 u; };

__device__ __forceinline__ unsigned f2tf32(float x) {
    unsigned r;
    asm("cvt.rna.tf32.f32 %0, %1;" : "=r"(r) : "f"(x));
    return r;
}

// ---------------------------------------------------------------------------
// Prepass: pack BOTH weight tensors into tf32 mma B-fragment order.
// ---------------------------------------------------------------------------
#define NPACK_OFF (25 * 4 * 13 * 32 * 2)
#define NPACK_DCN (25 * 2 * 4 * 4 * 32 * 2)

__global__ void pack_weights_kernel(const float* __restrict__ w_off,
                                    const float* __restrict__ w_dcn)
{
    int idx = blockIdx.x * 256 + threadIdx.x;
    if (idx < NPACK_OFF) {
        int r    = idx & 1;
        int lane = (idx >> 1) & 31;
        int rem  = idx >> 6;
        int t    = rem % 13;
        int s    = (rem / 13) % 4;
        int k    = rem / (13 * 4);
        int tig  = lane & 3;
        int g8   = lane >> 2;
        int c    = 8 * s + tig + 4 * r;
        int ch   = 8 * t + g8;
        float v  = (ch < 100) ? w_off[k * 3200 + c * 100 + ch] : 0.0f;
        g_bpack[idx] = f2tf32(v);
    } else if (idx < NPACK_OFF + NPACK_DCN) {
        int j    = idx - NPACK_OFF;
        int r    = j & 1;
        int lane = (j >> 1) & 31;
        int rem  = j >> 6;
        int t    = rem % 4;
        int s    = (rem / 4) % 4;
        int g    = (rem / 16) % 2;
        int k    = rem / 32;
        int tig  = lane & 3;
        int g8   = lane >> 2;
        int c    = 8 * s + tig + 4 * r;
        int o    = 32 * g + 8 * t + g8;
        g_wdpack[j] = f2tf32(w_dcn[k * 2048 + c * 64 + o]);
    }
}

// ---------------------------------------------------------------------------
// Kernel A v8b: offset conv via tf32 mma.sync.m16n8k8.
// Only change vs v8: __launch_bounds__(128, 6) -> 6 blocks/SM, 888 blocks
// per wave vs grid 900 => ~1.01 waves (was 1.22).
// ---------------------------------------------------------------------------
#define PXS 36   // pixel stride in patch (floats)

__global__ __launch_bounds__(128, 6)
void offset_conv_kernel(const float* __restrict__ vol,
                        const float* __restrict__ b_off)
{
    __shared__ float patch[16 * 16 * PXS];   // 36.9 KB

    const int tid  = threadIdx.x;
    const int lane = tid & 31;
    const int warp = tid >> 5;
    const int ox0 = blockIdx.x * 8;
    const int oy0 = blockIdx.y * 8;
    const int b   = blockIdx.z;

    for (int idx = tid; idx < 2048; idx += 128) {
        int row = idx >> 7;
        int rem = idx & 127;
        int col = rem >> 3;
        int c4  = rem & 7;
        const float4 v = *reinterpret_cast<const float4*>(
            vol + ((size_t)((b * H_ + oy0 + row) * W_ + ox0 + col)) * C_ + 4 * c4);
        *reinterpret_cast<float4*>(&patch[(row * 16 + col) * PXS + 4 * c4]) = v;
    }
    __syncthreads();

    const int g   = lane >> 2;
    const int tig = lane & 3;

    float cacc[13][4];
#pragma unroll
    for (int t = 0; t < 13; ++t)
#pragma unroll
        for (int i = 0; i < 4; ++i) cacc[t][i] = 0.0f;

    const unsigned* bp = g_bpack + 2 * lane;

#pragma unroll 1
    for (int k = 0; k < 25; ++k) {
        const int fy2 = (k / 5) * 2, fx2 = (k % 5) * 2;
        const float* pa0 = &patch[((2 * warp + fy2) * 16 + fx2 + g) * PXS];
        const float* pa1 = pa0 + 16 * PXS;

#pragma unroll
        for (int s = 0; s < 4; ++s) {
            unsigned a0 = f2tf32(pa0[8 * s + tig]);
            unsigned a1 = f2tf32(pa1[8 * s + tig]);
            unsigned a2 = f2tf32(pa0[8 * s + tig + 4]);
            unsigned a3 = f2tf32(pa1[8 * s + tig + 4]);
            const uint2* bks = reinterpret_cast<const uint2*>(
                bp + ((k * 4 + s) * 13) * 64);
#pragma unroll
            for (int t = 0; t < 13; ++t) {
                uint2 bb = __ldg(bks + t * 32);
                asm volatile(
                    "mma.sync.aligned.m16n8k8.row.col.f32.tf32.tf32.f32 "
                    "{%0,%1,%2,%3}, {%4,%5,%6,%7}, {%8,%9}, {%0,%1,%2,%3};"
                    : "+f"(cacc[t][0]), "+f"(cacc[t][1]),
                      "+f"(cacc[t][2]), "+f"(cacc[t][3])
                    : "r"(a0), "r"(a1), "r"(a2), "r"(a3),
                      "r"(bb.x), "r"(bb.y));
            }
        }
    }

    const int oyA = oy0 + 2 * warp;
    const int oxA = ox0 + g;
    float* outA = &g_offbuf[((size_t)((b * OH_ + oyA) * OW_ + oxA)) * OCH_];
    float* outB = outA + (size_t)OW_ * OCH_;
#pragma unroll
    for (int t = 0; t < 13; ++t) {
        int ch0 = 8 * t + 2 * tig;
        if (ch0 < 100) {
            float2 bo = *reinterpret_cast<const float2*>(b_off + ch0);
            *reinterpret_cast<float2*>(outA + ch0) =
                make_float2(cacc[t][0] + bo.x, cacc[t][1] + bo.y);
            *reinterpret_cast<float2*>(outB + ch0) =
                make_float2(cacc[t][2] + bo.x, cacc[t][3] + bo.y);
        }
    }
}

// ---------------------------------------------------------------------------
// Kernel B v8 (EXACT R12 revert, measured ~132us): gather + tf32 MMA GEMM,
// smem-staged offsets, tf32 conversion in the gather, double-buffered Ss,
// 1 sync/tap, (128,7).
// ---------------------------------------------------------------------------
#define GST (32 * PXS + 8)    // 1160: group stride in Ss
#define OFS 104               // offset row stride (floats)

__global__ __launch_bounds__(128, 7)
void dcn_kernel(const float* __restrict__ vol,
                const float* __restrict__ b_dcn,
                float* __restrict__ out)
{
    __shared__ __align__(16) float Ss[2][2 * GST];   // 18.6 KB (tf32 bits)
    __shared__ __align__(16) float offS[32 * OFS];   // 13.3 KB

    const int tid  = threadIdx.x;
    const int lane = tid & 31;
    const int warp = tid >> 5;
    const int ox0 = blockIdx.x * 8;
    const int oy0 = blockIdx.y * 4;
    const int b   = blockIdx.z;

    // GEMM roles
    const int gw  = warp >> 1;
    const int mh  = warp & 1;
    const int g8  = lane >> 2;
    const int tig = lane & 3;

    // Gather roles
    const int q = lane >> 3;
    const int j = lane & 7;
    const int sBase = warp * 16;

    const float* volb = vol + (size_t)b * (H_ * W_ * C_);
    const float* offb = g_offbuf + ((size_t)(b * OH_ + oy0) * OW_ + ox0) * OCH_;

    // Stage the tile's 32x100 offsets once (L2 -> smem)
    for (int idx = tid; idx < 3200; idx += 128) {
        int p  = idx / 100;
        int ch = idx - p * 100;
        int pyi = p >> 3, pxi = p & 7;
        offS[p * OFS + ch] = __ldg(offb + (pyi * OW_ + pxi) * OCH_ + ch);
    }
    __syncthreads();

    float cacc[4][4];
#pragma unroll
    for (int t = 0; t < 4; ++t)
#pragma unroll
        for (int i = 0; i < 4; ++i) cacc[t][i] = 0.0f;

    const unsigned* wdp = g_wdpack + 2 * lane;

#pragma unroll 1
    for (int k = 0; k < 25; ++k) {
        float* Sb = Ss[k & 1];

        const int fy = k / 5, fx = k - fy * 5;
        const float dky = (float)((fy - 2) * 2);
        const float dkx = (float)((fx - 2) * 2);

        // Gather 64 samples (warp-cooperative, full-line LDG.128)
#pragma unroll
        for (int pass = 0; pass < 4; ++pass) {
            int s = sBase + pass * 4 + q;
            int p = s & 31, g2 = s >> 5;
            int pyi = p >> 3, pxi = p & 7;

            // offsets from smem (LDS, ~29 cyc instead of L2 LDG ~234)
            float4 ov = *reinterpret_cast<const float4*>(&offS[p * OFS + 4 * k]);
            float offy = g2 ? ov.y : ov.x;
            float offx = g2 ? ov.w : ov.z;

            float py = (float)(oy0 + pyi + 4) + dky + offy;
            float px = (float)(ox0 + pxi + 4) + dkx + offx;
            py = fminf(fmaxf(py, 0.0f), 127.0f);
            px = fminf(fmaxf(px, 0.0f), 127.0f);
            float y0f = fminf(floorf(py), 126.0f);
            float x0f = fminf(floorf(px), 126.0f);
            float wy = py - y0f, wx = px - x0f;
            int y0 = (int)y0f, x0 = (int)x0f;

            const float4* r0 = reinterpret_cast<const float4*>(
                volb + ((size_t)(y0 * W_ + x0)) * C_);
            f4u L0, L1, L2, L3;
            L0.f = r0[j];
            L1.f = r0[j + 8];
            L2.f = r0[j + 1024];
            L3.f = r0[j + 1032];

            u64t c00p = dup2((1.0f - wy) * (1.0f - wx));
            u64t c01p = dup2((1.0f - wy) * wx);
            u64t c10p = dup2(wy * (1.0f - wx));
            u64t c11p = dup2(wy * wx);

            ulonglong2 svu;
            svu.x = ffma2(L0.u.x, c00p, ffma2(L1.u.x, c01p,
                        ffma2(L2.u.x, c10p, fmul2(L3.u.x, c11p))));
            svu.y = ffma2(L0.u.y, c00p, ffma2(L1.u.y, c01p,
                        ffma2(L2.u.y, c10p, fmul2(L3.u.y, c11p))));
            float2 s01 = up2(svu.x);
            float2 s23 = up2(svu.y);

            // convert to tf32 here; GEMM A-frag becomes a bare LDS.32
            uint4 sv;
            sv.x = f2tf32(s01.x);
            sv.y = f2tf32(s01.y);
            sv.z = f2tf32(s23.x);
            sv.w = f2tf32(s23.y);
            *reinterpret_cast<uint4*>(&Sb[g2 * GST + p * PXS + 4 * j]) = sv;
        }
        __syncthreads();

        // GEMM via tf32 MMA: M=16 px, N=32 out (4 n-tiles), K=32 (4 steps)
        const unsigned* Sg  = reinterpret_cast<const unsigned*>(
            Sb + gw * GST + (16 * mh + g8) * PXS);
        const unsigned* Sg8 = Sg + 8 * PXS;
        const unsigned* wk = wdp + ((k * 2 + gw) * 16) * 64;
#pragma unroll
        for (int s = 0; s < 4; ++s) {
            unsigned a0 = Sg [8 * s + tig];
            unsigned a1 = Sg8[8 * s + tig];
            unsigned a2 = Sg [8 * s + tig + 4];
            unsigned a3 = Sg8[8 * s + tig + 4];
            const uint2* bks = reinterpret_cast<const uint2*>(wk + (s * 4) * 64);
#pragma unroll
            for (int t = 0; t < 4; ++t) {
                uint2 bb = __ldg(bks + t * 32);
                asm volatile(
                    "mma.sync.aligned.m16n8k8.row.col.f32.tf32.tf32.f32 "
                    "{%0,%1,%2,%3}, {%4,%5,%6,%7}, {%8,%9}, {%0,%1,%2,%3};"
                    : "+f"(cacc[t][0]), "+f"(cacc[t][1]),
                      "+f"(cacc[t][2]), "+f"(cacc[t][3])
                    : "r"(a0), "r"(a1), "r"(a2), "r"(a3),
                      "r"(bb.x), "r"(bb.y));
            }
        }
    }

    // Epilogue: C rows = px 16mh+g8 (+8), cols = out 32gw+8t+2tig (+1)
    const int pA = 16 * mh + g8;
    const int pB = pA + 8;
    const int oyA = oy0 + (pA >> 3), oxA = ox0 + (pA & 7);
    const int oyB = oy0 + (pB >> 3), oxB = ox0 + (pB & 7);
    float* outA = out + ((size_t)((b * OH_ + oyA) * OW_ + oxA)) * F_;
    float* outB = out + ((size_t)((b * OH_ + oyB) * OW_ + oxB)) * F_;
#pragma unroll
    for (int t = 0; t < 4; ++t) {
        int o0 = 32 * gw + 8 * t + 2 * tig;
        float2 bo = __ldg(reinterpret_cast<const float2*>(b_dcn + o0));
        *reinterpret_cast<float2*>(outA + o0) =
            make_float2(cacc[t][0] + bo.x, cacc[t][1] + bo.y);
        *reinterpret_cast<float2*>(outB + o0) =
            make_float2(cacc[t][2] + bo.x, cacc[t][3] + bo.y);
    }
}

// ---------------------------------------------------------------------------
extern "C" void kernel_launch(void* const* d_in, const int* in_sizes, int n_in,
                              void* d_out, int out_size)
{
    const float* vol   = (const float*)d_in[0];
    const float* w_off = (const float*)d_in[1];
    const float* b_off = (const float*)d_in[2];
    const float* w_dcn = (const float*)d_in[3];
    const float* b_dcn = (const float*)d_in[4];
    float* out = (float*)d_out;

    pack_weights_kernel<<<(NPACK_OFF + NPACK_DCN + 255) / 256, 256>>>(w_off, w_dcn);

    dim3 gA(OW_ / 8, OH_ / 8, B_);   // (15, 15, 4)
    offset_conv_kernel<<<gA, 128>>>(vol, b_off);

    dim3 gB(OW_ / 8, OH_ / 4, B_);   // (15, 30, 4) = 1800 blocks
    dcn_kernel<<<gB, 128>>>(vol, b_dcn, out);
}

// round 16
// speedup vs baseline: 1.7986x; 1.2616x over previous
#include <cuda_runtime.h>

// Problem constants
#define H_   128
#define W_   128
#define C_   32
#define B_   4
#define OH_  120
#define OW_  120
#define OCH_ 100
#define F_   64

__device__ float g_offbuf[(size_t)B_ * OH_ * OW_ * OCH_];
// fp16 fragment-ordered offset-conv weights: [k][s2][t13][lane][r]
__device__ unsigned g_bpackH[25 * 2 * 13 * 32 * 2];     // 41600
// fp16 fragment-ordered dcn weights: [k][g][s2][t4][lane][r]
__device__ unsigned g_wdpackH[25 * 2 * 2 * 4 * 32 * 2]; // 25600

// ---- packed f32x2 helpers --------------------------------------------------
typedef unsigned long long u64t;

__device__ __forceinline__ u64t ffma2(u64t a, u64t b, u64t c) {
    u64t d;
    asm("fma.rn.f32x2 %0, %1, %2, %3;" : "=l"(d) : "l"(a), "l"(b), "l"(c));
    return d;
}
__device__ __forceinline__ u64t fmul2(u64t a, u64t b) {
    u64t d;
    asm("mul.rn.f32x2 %0, %1, %2;" : "=l"(d) : "l"(a), "l"(b));
    return d;
}
__device__ __forceinline__ u64t dup2(float x) {
    u64t d; unsigned xi = __float_as_uint(x);
    asm("mov.b64 %0, {%1, %1};" : "=l"(d) : "r"(xi));
    return d;
}
__device__ __forceinline__ float2 up2(u64t v) {
    float2 f;
    asm("mov.b64 {%0, %1}, %2;" : "=f"(f.x), "=f"(f.y) : "l"(v));
    return f;
}
union f4u { float4 f; ulonglong2 u; };

// pack two f32 -> f16x2 word {lo, hi}
__device__ __forceinline__ unsigned h2u(float lo, float hi) {
    unsigned d;
    asm("cvt.rn.f16x2.f32 %0, %1, %2;" : "=r"(d) : "f"(hi), "f"(lo));
    return d;
}

#define MMA_F16(c0,c1,c2,c3,a0,a1,a2,a3,b0,b1)                                \
    asm volatile(                                                             \
        "mma.sync.aligned.m16n8k16.row.col.f32.f16.f16.f32 "                  \
        "{%0,%1,%2,%3}, {%4,%5,%6,%7}, {%8,%9}, {%0,%1,%2,%3};"               \
        : "+f"(c0), "+f"(c1), "+f"(c2), "+f"(c3)                              \
        : "r"(a0), "r"(a1), "r"(a2), "r"(a3), "r"(b0), "r"(b1))

// ---------------------------------------------------------------------------
// Prepass: pack BOTH weight tensors into fp16 m16n8k16 B-fragment order.
// b_r covers K-rows {16*s2 + 2*tig + 8*r, +1} at N-col g8.
// ---------------------------------------------------------------------------
#define NPACK_OFF_H (25 * 2 * 13 * 32 * 2)
#define NPACK_DCN_H (25 * 2 * 2 * 4 * 32 * 2)

__global__ void pack_weights_kernel(const float* __restrict__ w_off,
                                    const float* __restrict__ w_dcn)
{
    int idx = blockIdx.x * 256 + threadIdx.x;
    if (idx < NPACK_OFF_H) {
        int r    = idx & 1;
        int lane = (idx >> 1) & 31;
        int rem  = idx >> 6;
        int t    = rem % 13;
        int s2   = (rem / 13) % 2;
        int k    = rem / 26;
        int tig  = lane & 3;
        int g8   = lane >> 2;
        int c0   = 16 * s2 + 2 * tig + 8 * r;
        int ch   = 8 * t + g8;
        float lo = (ch < 100) ? w_off[k * 3200 + c0 * 100 + ch] : 0.0f;
        float hi = (ch < 100) ? w_off[k * 3200 + (c0 + 1) * 100 + ch] : 0.0f;
        g_bpackH[idx & ~1 | 0] = g_bpackH[idx];  // placeholder avoided below
    }
    // (rewritten cleanly below to avoid aliasing confusion)
}

__global__ void pack_weights2_kernel(const float* __restrict__ w_off,
                                     const float* __restrict__ w_dcn)
{
    int idx = blockIdx.x * 256 + threadIdx.x;
    if (idx < NPACK_OFF_H) {
        int r    = idx & 1;
        int lane = (idx >> 1) & 31;
        int rem  = idx >> 6;
        int t    = rem % 13;
        int s2   = (rem / 13) % 2;
        int k    = rem / 26;
        int tig  = lane & 3;
        int g8   = lane >> 2;
        int c0   = 16 * s2 + 2 * tig + 8 * r;
        int ch   = 8 * t + g8;
        float lo = (ch < 100) ? w_off[k * 3200 + c0 * 100 + ch] : 0.0f;
        float hi = (ch < 100) ? w_off[k * 3200 + (c0 + 1) * 100 + ch] : 0.0f;
        g_bpackH[idx] = h2u(lo, hi);
    } else if (idx < NPACK_OFF_H + NPACK_DCN_H) {
        int j    = idx - NPACK_OFF_H;
        int r    = j & 1;
        int lane = (j >> 1) & 31;
        int rem  = j >> 6;
        int t    = rem % 4;
        int s2   = (rem / 4) % 2;
        int g    = (rem / 8) % 2;
        int k    = rem / 16;
        int tig  = lane & 3;
        int g8   = lane >> 2;
        int c0   = 16 * s2 + 2 * tig + 8 * r;
        int o    = 32 * g + 8 * t + g8;
        float lo = w_dcn[k * 2048 + c0 * 64 + o];
        float hi = w_dcn[k * 2048 + (c0 + 1) * 64 + o];
        g_wdpackH[j] = h2u(lo, hi);
    }
}

// ---------------------------------------------------------------------------
// Kernel A v9: offset conv via fp16 mma.sync.m16n8k16.
// Patch in smem as half2 words, pixel stride 20 words (conflict-free A-frag
// LDS: 20*g8+tig distinct mod 32). Per tap: 2 k-steps x 13 n-tiles = 26 MMA.
// ---------------------------------------------------------------------------
#define PXH 20   // half2-words per pixel (16 data + 4 pad)

__global__ __launch_bounds__(128, 6)
void offset_conv_kernel(const float* __restrict__ vol,
                        const float* __restrict__ b_off)
{
    __shared__ unsigned patchH[16 * 16 * PXH];   // 20.5 KB

    const int tid  = threadIdx.x;
    const int lane = tid & 31;
    const int warp = tid >> 5;
    const int ox0 = blockIdx.x * 8;
    const int oy0 = blockIdx.y * 8;
    const int b   = blockIdx.z;

    // Load patch, converting f32 -> half2 on store
    for (int idx = tid; idx < 2048; idx += 128) {
        int row = idx >> 7;
        int rem = idx & 127;
        int col = rem >> 3;
        int c4  = rem & 7;
        const float4 v = *reinterpret_cast<const float4*>(
            vol + ((size_t)((b * H_ + oy0 + row) * W_ + ox0 + col)) * C_ + 4 * c4);
        uint2 hv;
        hv.x = h2u(v.x, v.y);
        hv.y = h2u(v.z, v.w);
        *reinterpret_cast<uint2*>(&patchH[(row * 16 + col) * PXH + 2 * c4]) = hv;
    }
    __syncthreads();

    const int g   = lane >> 2;
    const int tig = lane & 3;

    float cacc[13][4];
#pragma unroll
    for (int t = 0; t < 13; ++t)
#pragma unroll
        for (int i = 0; i < 4; ++i) cacc[t][i] = 0.0f;

    const uint2* wb = reinterpret_cast<const uint2*>(g_bpackH);

#pragma unroll 1
    for (int k = 0; k < 25; ++k) {
        const int fy2 = (k / 5) * 2, fx2 = (k % 5) * 2;
        const unsigned* pa0 = &patchH[((2 * warp + fy2) * 16 + fx2 + g) * PXH];
        const unsigned* pa1 = pa0 + 16 * PXH;

#pragma unroll
        for (int s2 = 0; s2 < 2; ++s2) {
            unsigned a0 = pa0[8 * s2 + tig];
            unsigned a1 = pa1[8 * s2 + tig];
            unsigned a2 = pa0[8 * s2 + tig + 4];
            unsigned a3 = pa1[8 * s2 + tig + 4];
            const uint2* bks = wb + ((k * 2 + s2) * 13) * 32 + lane;
#pragma unroll
            for (int t = 0; t < 13; ++t) {
                uint2 bb = __ldg(bks + t * 32);
                MMA_F16(cacc[t][0], cacc[t][1], cacc[t][2], cacc[t][3],
                        a0, a1, a2, a3, bb.x, bb.y);
            }
        }
    }

    const int oyA = oy0 + 2 * warp;
    const int oxA = ox0 + g;
    float* outA = &g_offbuf[((size_t)((b * OH_ + oyA) * OW_ + oxA)) * OCH_];
    float* outB = outA + (size_t)OW_ * OCH_;
#pragma unroll
    for (int t = 0; t < 13; ++t) {
        int ch0 = 8 * t + 2 * tig;
        if (ch0 < 100) {
            float2 bo = *reinterpret_cast<const float2*>(b_off + ch0);
            *reinterpret_cast<float2*>(outA + ch0) =
                make_float2(cacc[t][0] + bo.x, cacc[t][1] + bo.y);
            *reinterpret_cast<float2*>(outB + ch0) =
                make_float2(cacc[t][2] + bo.x, cacc[t][3] + bo.y);
        }
    }
}

// ---------------------------------------------------------------------------
// Kernel B v11: gather + fp16 MMA GEMM.
// Ss stores half2 words ([g][px][c2], px stride 20 words, conflict-free);
// per tap: 2 k-steps x 4 n-tiles = 8 MMAs. Offsets smem-staged; Ss double-
// buffered; 1 sync/tap.
// ---------------------------------------------------------------------------
#define GSTH (32 * PXH + 8)   // 648 words: group stride
#define OFS  104              // offset row stride (floats)

__global__ __launch_bounds__(128, 7)
void dcn_kernel(const float* __restrict__ vol,
                const float* __restrict__ b_dcn,
                float* __restrict__ out)
{
    __shared__ __align__(16) unsigned SsH[2][2 * GSTH];   // 10.4 KB
    __shared__ __align__(16) float offS[32 * OFS];        // 13.3 KB

    const int tid  = threadIdx.x;
    const int lane = tid & 31;
    const int warp = tid >> 5;
    const int ox0 = blockIdx.x * 8;
    const int oy0 = blockIdx.y * 4;
    const int b   = blockIdx.z;

    // GEMM roles
    const int gw  = warp >> 1;
    const int mh  = warp & 1;
    const int g8  = lane >> 2;
    const int tig = lane & 3;

    // Gather roles
    const int q = lane >> 3;
    const int j = lane & 7;
    const int sBase = warp * 16;

    const float* volb = vol + (size_t)b * (H_ * W_ * C_);
    const float* offb = g_offbuf + ((size_t)(b * OH_ + oy0) * OW_ + ox0) * OCH_;

    // Stage the tile's 32x100 offsets once
    for (int idx = tid; idx < 3200; idx += 128) {
        int p  = idx / 100;
        int ch = idx - p * 100;
        int pyi = p >> 3, pxi = p & 7;
        offS[p * OFS + ch] = __ldg(offb + (pyi * OW_ + pxi) * OCH_ + ch);
    }
    __syncthreads();

    float cacc[4][4];
#pragma unroll
    for (int t = 0; t < 4; ++t)
#pragma unroll
        for (int i = 0; i < 4; ++i) cacc[t][i] = 0.0f;

    const uint2* wb2 = reinterpret_cast<const uint2*>(g_wdpackH);

#pragma unroll 1
    for (int k = 0; k < 25; ++k) {
        unsigned* Sb = SsH[k & 1];

        const int fy = k / 5, fx = k - fy * 5;
        const float dky = (float)((fy - 2) * 2);
        const float dkx = (float)((fx - 2) * 2);

        // Gather 64 samples (warp-cooperative, full-line LDG.128)
#pragma unroll
        for (int pass = 0; pass < 4; ++pass) {
            int s = sBase + pass * 4 + q;
            int p = s & 31, g2 = s >> 5;
            int pyi = p >> 3, pxi = p & 7;

            float4 ov = *reinterpret_cast<const float4*>(&offS[p * OFS + 4 * k]);
            float offy = g2 ? ov.y : ov.x;
            float offx = g2 ? ov.w : ov.z;

            float py = (float)(oy0 + pyi + 4) + dky + offy;
            float px = (float)(ox0 + pxi + 4) + dkx + offx;
            py = fminf(fmaxf(py, 0.0f), 127.0f);
            px = fminf(fmaxf(px, 0.0f), 127.0f);
            float y0f = fminf(floorf(py), 126.0f);
            float x0f = fminf(floorf(px), 126.0f);
            float wy = py - y0f, wx = px - x0f;
            int y0 = (int)y0f, x0 = (int)x0f;

            const float4* r0 = reinterpret_cast<const float4*>(
                volb + ((size_t)(y0 * W_ + x0)) * C_);
            f4u L0, L1, L2, L3;
            L0.f = r0[j];
            L1.f = r0[j + 8];
            L2.f = r0[j + 1024];
            L3.f = r0[j + 1032];

            u64t c00p = dup2((1.0f - wy) * (1.0f - wx));
            u64t c01p = dup2((1.0f - wy) * wx);
            u64t c10p = dup2(wy * (1.0f - wx));
            u64t c11p = dup2(wy * wx);

            ulonglong2 svu;
            svu.x = ffma2(L0.u.x, c00p, ffma2(L1.u.x, c01p,
                        ffma2(L2.u.x, c10p, fmul2(L3.u.x, c11p))));
            svu.y = ffma2(L0.u.y, c00p, ffma2(L1.u.y, c01p,
                        ffma2(L2.u.y, c10p, fmul2(L3.u.y, c11p))));
            float2 s01 = up2(svu.x);
            float2 s23 = up2(svu.y);

            // channels 4j..4j+3 of sample p -> 2 half2 words
            uint2 hv;
            hv.x = h2u(s01.x, s01.y);
            hv.y = h2u(s23.x, s23.y);
            *reinterpret_cast<uint2*>(&Sb[g2 * GSTH + p * PXH + 2 * j]) = hv;
        }
        __syncthreads();

        // GEMM via fp16 MMA: M=16 px, N=32 out (4 n-tiles), K=32 (2 k16-steps)
        const unsigned* Sg  = Sb + gw * GSTH + (16 * mh + g8) * PXH;
        const unsigned* Sg8 = Sg + 8 * PXH;
#pragma unroll
        for (int s2 = 0; s2 < 2; ++s2) {
            unsigned a0 = Sg [8 * s2 + tig];
            unsigned a1 = Sg8[8 * s2 + tig];
            unsigned a2 = Sg [8 * s2 + tig + 4];
            unsigned a3 = Sg8[8 * s2 + tig + 4];
            const uint2* bks = wb2 + (((k * 2 + gw) * 2 + s2) * 4) * 32 + lane;
#pragma unroll
            for (int t = 0; t < 4; ++t) {
                uint2 bb = __ldg(bks + t * 32);
                MMA_F16(cacc[t][0], cacc[t][1], cacc[t][2], cacc[t][3],
                        a0, a1, a2, a3, bb.x, bb.y);
            }
        }
    }

    // Epilogue: C rows = px 16mh+g8 (+8), cols = out 32gw+8t+2tig (+1)
    const int pA = 16 * mh + g8;
    const int pB = pA + 8;
    const int oyA = oy0 + (pA >> 3), oxA = ox0 + (pA & 7);
    const int oyB = oy0 + (pB >> 3), oxB = ox0 + (pB & 7);
    float* outA = out + ((size_t)((b * OH_ + oyA) * OW_ + oxA)) * F_;
    float* outB = out + ((size_t)((b * OH_ + oyB) * OW_ + oxB)) * F_;
#pragma unroll
    for (int t = 0; t < 4; ++t) {
        int o0 = 32 * gw + 8 * t + 2 * tig;
        float2 bo = __ldg(reinterpret_cast<const float2*>(b_dcn + o0));
        *reinterpret_cast<float2*>(outA + o0) =
            make_float2(cacc[t][0] + bo.x, cacc[t][1] + bo.y);
        *reinterpret_cast<float2*>(outB + o0) =
            make_float2(cacc[t][2] + bo.x, cacc[t][3] + bo.y);
    }
}

// ---------------------------------------------------------------------------
extern "C" void kernel_launch(void* const* d_in, const int* in_sizes, int n_in,
                              void* d_out, int out_size)
{
    const float* vol   = (const float*)d_in[0];
    const float* w_off = (const float*)d_in[1];
    const float* b_off = (const float*)d_in[2];
    const float* w_dcn = (const float*)d_in[3];
    const float* b_dcn = (const float*)d_in[4];
    float* out = (float*)d_out;

    pack_weights2_kernel<<<(NPACK_OFF_H + NPACK_DCN_H + 255) / 256, 256>>>(
        w_off, w_dcn);

    dim3 gA(OW_ / 8, OH_ / 8, B_);   // (15, 15, 4)
    offset_conv_kernel<<<gA, 128>>>(vol, b_off);

    dim3 gB(OW_ / 8, OH_ / 4, B_);   // (15, 30, 4) = 1800 blocks
    dcn_kernel<<<gB, 128>>>(vol, b_dcn, out);
}